// round 2
// baseline (speedup 1.0000x reference)
#include <cuda_runtime.h>
#include <cuda_bf16.h>

#define NN_MAX 50000
#define NE_MAX 800000
#define HID 128

// scratch (device globals — no allocation allowed)
__device__ int   g_deg[NN_MAX];
__device__ int   g_off[NN_MAX + 1];
__device__ int   g_cursor[NN_MAX];
__device__ int   g_adj[NE_MAX];
__device__ float g_dinv[NN_MAX];
__device__ float g_ht[NN_MAX * HID];
__device__ float g_act[NN_MAX * HID];
__device__ int   g_part[256];

// ---------------- CSR build ----------------

__global__ void k_count(const int* __restrict__ dst, int* deg, int E) {
    int e = blockIdx.x * blockDim.x + threadIdx.x;
    if (e < E) atomicAdd(&deg[dst[e]], 1);
}

// per-block exclusive scan of deg chunk -> off, block sums -> part
__global__ void k_scan_block(const int* __restrict__ deg, int* off, int* part, int n) {
    __shared__ int s[256];
    int tid = threadIdx.x;
    int gid = blockIdx.x * 256 + tid;
    int v = (gid < n) ? deg[gid] : 0;
    s[tid] = v;
    __syncthreads();
    #pragma unroll
    for (int d = 1; d < 256; d <<= 1) {
        int t = 0;
        if (tid >= d) t = s[tid - d];
        __syncthreads();
        s[tid] += t;
        __syncthreads();
    }
    if (gid < n) off[gid] = s[tid] - v;   // exclusive within block
    if (tid == 255) part[blockIdx.x] = s[255];
}

// parallel exclusive scan of block partials (nb <= 256)
__global__ void k_scan_partials(int* part, int nb) {
    __shared__ int s[256];
    int tid = threadIdx.x;
    int v = (tid < nb) ? part[tid] : 0;
    s[tid] = v;
    __syncthreads();
    #pragma unroll
    for (int d = 1; d < 256; d <<= 1) {
        int t = (tid >= d) ? s[tid - d] : 0;
        __syncthreads();
        s[tid] += t;
        __syncthreads();
    }
    if (tid < nb) part[tid] = s[tid] - v;  // exclusive
}

__global__ void k_finalize(int* off, const int* __restrict__ part, int* cursor,
                           const int* __restrict__ deg, float* dinv, int n, int E) {
    int gid = blockIdx.x * 256 + threadIdx.x;
    if (gid < n) {
        int o = off[gid] + part[blockIdx.x];
        off[gid] = o;
        cursor[gid] = o;
        dinv[gid] = rsqrtf((float)(deg[gid] + 1));  // +1 self loop
    }
    if (gid == 0) off[n] = E;
}

__global__ void k_fill_adj(const int* __restrict__ src, const int* __restrict__ dst,
                           int* cursor, int* adj, int E) {
    int e = blockIdx.x * blockDim.x + threadIdx.x;
    if (e < E) {
        int d = dst[e];
        int pos = atomicAdd(&cursor[d], 1);
        adj[pos] = src[e];
    }
}

// ---------------- GEMM: out[i,:] = (X[i,:] @ W) * dinv[i] ----------------
// fp32x2 packed FMA (FFMA2). Block = 256 threads, 64 rows x 128 cols.
// Thread tile: 4 rows x 8 cols (4 packed col-pairs).
// smem: Xs 64x128 (32KB) + Ws 32x128 chunk (16KB) = 48KB static.

__device__ __forceinline__ void ffma2(unsigned long long& d,
                                      unsigned long long a,
                                      unsigned long long b) {
    asm("fma.rn.f32x2 %0, %1, %2, %0;" : "+l"(d) : "l"(a), "l"(b));
}

__global__ __launch_bounds__(256) void k_gemm(const float* __restrict__ X,
                                              const float* __restrict__ W,
                                              const float* __restrict__ dinv,
                                              float* __restrict__ out, int n) {
    __shared__ float Xs[64 * 128];
    __shared__ float Ws[32 * 128];
    float4* Xs4 = reinterpret_cast<float4*>(Xs);
    float4* Ws4 = reinterpret_cast<float4*>(Ws);
    const float4* Xg = reinterpret_cast<const float4*>(X);
    const float4* Wg = reinterpret_cast<const float4*>(W);

    int tid = threadIdx.x;
    int row0 = blockIdx.x * 64;

    // load X tile (64 rows x 128 cols = 2048 float4s), guarded
    #pragma unroll
    for (int t = 0; t < 8; ++t) {
        int idx = tid + t * 256;
        int r = idx >> 5;
        int c4 = idx & 31;
        int grow = row0 + r;
        float4 v = make_float4(0.f, 0.f, 0.f, 0.f);
        if (grow < n) v = Xg[grow * 32 + c4];
        Xs4[idx] = v;
    }

    unsigned long long acc[4][4];   // [row][col-pair]
    #pragma unroll
    for (int r = 0; r < 4; ++r)
        #pragma unroll
        for (int c = 0; c < 4; ++c) acc[r][c] = 0ull;

    int tcf = (tid & 15) * 8;       // col base (floats)
    int tr  = (tid >> 4) * 4;       // row base within tile

    #pragma unroll
    for (int kt = 0; kt < 4; ++kt) {
        __syncthreads();
        // load W chunk rows [kt*32, kt*32+32)
        #pragma unroll
        for (int t = 0; t < 4; ++t) {
            int idx = tid + t * 256;
            Ws4[idx] = Wg[kt * 1024 + idx];
        }
        __syncthreads();
        #pragma unroll
        for (int k4 = 0; k4 < 8; ++k4) {
            // x values for 4 rows, 4 consecutive k — one float4 per row
            float4 xv[4];
            #pragma unroll
            for (int r = 0; r < 4; ++r)
                xv[r] = Xs4[(tr + r) * 32 + kt * 8 + k4];
            #pragma unroll
            for (int kk = 0; kk < 4; ++kk) {
                int k = k4 * 4 + kk;
                // w pairs for 8 cols: two float4 loads -> 4 b64 pairs
                float4 wA = *reinterpret_cast<const float4*>(Ws + k * 128 + tcf);
                float4 wB = *reinterpret_cast<const float4*>(Ws + k * 128 + tcf + 4);
                unsigned long long w0, w1, w2, w3;
                asm("mov.b64 %0, {%1, %2};" : "=l"(w0) : "f"(wA.x), "f"(wA.y));
                asm("mov.b64 %0, {%1, %2};" : "=l"(w1) : "f"(wA.z), "f"(wA.w));
                asm("mov.b64 %0, {%1, %2};" : "=l"(w2) : "f"(wB.x), "f"(wB.y));
                asm("mov.b64 %0, {%1, %2};" : "=l"(w3) : "f"(wB.z), "f"(wB.w));
                #pragma unroll
                for (int r = 0; r < 4; ++r) {
                    float xs = (kk == 0) ? xv[r].x : (kk == 1) ? xv[r].y
                             : (kk == 2) ? xv[r].z : xv[r].w;
                    unsigned long long xx;
                    asm("mov.b64 %0, {%1, %1};" : "=l"(xx) : "f"(xs));
                    ffma2(acc[r][0], xx, w0);
                    ffma2(acc[r][1], xx, w1);
                    ffma2(acc[r][2], xx, w2);
                    ffma2(acc[r][3], xx, w3);
                }
            }
        }
    }

    float4* Og = reinterpret_cast<float4*>(out);
    #pragma unroll
    for (int r = 0; r < 4; ++r) {
        int grow = row0 + tr + r;
        if (grow < n) {
            float s = dinv[grow];
            float2 a0 = *reinterpret_cast<float2*>(&acc[r][0]);
            float2 a1 = *reinterpret_cast<float2*>(&acc[r][1]);
            float2 a2 = *reinterpret_cast<float2*>(&acc[r][2]);
            float2 a3 = *reinterpret_cast<float2*>(&acc[r][3]);
            float4 o0 = make_float4(a0.x * s, a0.y * s, a1.x * s, a1.y * s);
            float4 o1 = make_float4(a2.x * s, a2.y * s, a3.x * s, a3.y * s);
            Og[grow * 32 + (tcf >> 2)]     = o0;
            Og[grow * 32 + (tcf >> 2) + 1] = o1;
        }
    }
}

// ---------------- Aggregation + bias + LayerNorm + ReLU ----------------
// One 128-thread block per node. ht rows are pre-scaled by dinv[src].

__device__ __forceinline__ float block_reduce_128(float v, float* sh) {
    #pragma unroll
    for (int o = 16; o; o >>= 1) v += __shfl_xor_sync(0xffffffffu, v, o);
    int w = threadIdx.x >> 5;
    if ((threadIdx.x & 31) == 0) sh[w] = v;
    __syncthreads();
    float r = sh[0] + sh[1] + sh[2] + sh[3];
    __syncthreads();
    return r;
}

__global__ void k_agg_ln(const float* __restrict__ ht, const int* __restrict__ adj,
                         const int* __restrict__ off, const float* __restrict__ dinv,
                         const float* __restrict__ bias, const float* __restrict__ gamma,
                         const float* __restrict__ beta, float* __restrict__ out, int n) {
    __shared__ float sh[4];
    int i = blockIdx.x;
    if (i >= n) return;
    int c = threadIdx.x;

    float a = __ldg(&ht[i * HID + c]);   // self-loop term
    int s = __ldg(&off[i]), e = __ldg(&off[i + 1]);
    int p = s;
    // MLP-4 unrolled gather
    for (; p + 4 <= e; p += 4) {
        int j0 = __ldg(&adj[p]);
        int j1 = __ldg(&adj[p + 1]);
        int j2 = __ldg(&adj[p + 2]);
        int j3 = __ldg(&adj[p + 3]);
        float v0 = __ldg(&ht[j0 * HID + c]);
        float v1 = __ldg(&ht[j1 * HID + c]);
        float v2 = __ldg(&ht[j2 * HID + c]);
        float v3 = __ldg(&ht[j3 * HID + c]);
        a += v0 + v1 + v2 + v3;
    }
    for (; p < e; ++p) a += __ldg(&ht[__ldg(&adj[p]) * HID + c]);

    float v = a * dinv[i] + bias[c];

    float mu = block_reduce_128(v, sh) * (1.0f / 128.0f);
    float d = v - mu;
    float var = block_reduce_128(d * d, sh) * (1.0f / 128.0f);
    float r = d * rsqrtf(var + 1e-5f) * gamma[c] + beta[c];
    out[i * HID + c] = fmaxf(r, 0.0f);
}

// ---------------- launch ----------------

extern "C" void kernel_launch(void* const* d_in, const int* in_sizes, int n_in,
                              void* d_out, int out_size) {
    const float* x     = (const float*)d_in[0];
    const int*   edges = (const int*)d_in[1];
    const float* W1    = (const float*)d_in[2];
    const float* b1    = (const float*)d_in[3];
    const float* g1    = (const float*)d_in[4];
    const float* be1   = (const float*)d_in[5];
    const float* W2    = (const float*)d_in[6];
    const float* b2    = (const float*)d_in[7];
    const float* g2    = (const float*)d_in[8];
    const float* be2   = (const float*)d_in[9];
    float* out = (float*)d_out;

    int n = in_sizes[0] / HID;
    int E = in_sizes[1] / 2;
    const int* src = edges;
    const int* dst = edges + E;

    int *deg, *off, *cursor, *adj, *part;
    float *dinv, *ht, *act;
    cudaGetSymbolAddress((void**)&deg, g_deg);
    cudaGetSymbolAddress((void**)&off, g_off);
    cudaGetSymbolAddress((void**)&cursor, g_cursor);
    cudaGetSymbolAddress((void**)&adj, g_adj);
    cudaGetSymbolAddress((void**)&part, g_part);
    cudaGetSymbolAddress((void**)&dinv, g_dinv);
    cudaGetSymbolAddress((void**)&ht, g_ht);
    cudaGetSymbolAddress((void**)&act, g_act);

    int nbN = (n + 255) / 256;
    int nbE = (E + 255) / 256;
    int nbG = (n + 63) / 64;

    cudaMemsetAsync(deg, 0, n * sizeof(int));
    k_count<<<nbE, 256>>>(dst, deg, E);
    k_scan_block<<<nbN, 256>>>(deg, off, part, n);
    k_scan_partials<<<1, 256>>>(part, nbN);
    k_finalize<<<nbN, 256>>>(off, part, cursor, deg, dinv, n, E);
    k_fill_adj<<<nbE, 256>>>(src, dst, cursor, adj, E);

    // layer 1
    k_gemm<<<nbG, 256>>>(x, W1, dinv, ht, n);
    k_agg_ln<<<n, 128>>>(ht, adj, off, dinv, b1, g1, be1, act, n);
    // layer 2
    k_gemm<<<nbG, 256>>>(act, W2, dinv, ht, n);
    k_agg_ln<<<n, 128>>>(ht, adj, off, dinv, b2, g2, be2, out, n);
}

// round 3
// speedup vs baseline: 1.0805x; 1.0805x over previous
#include <cuda_runtime.h>
#include <cuda_bf16.h>

#define NN_MAX 50000
#define NE_MAX 800000
#define HID 128

// scratch (device globals — no allocation allowed)
__device__ int   g_deg[NN_MAX];
__device__ int   g_off[NN_MAX + 1];
__device__ int   g_cursor[NN_MAX];
__device__ int   g_adj[NE_MAX];
__device__ float g_dinv[NN_MAX];
__device__ float g_ht[NN_MAX * HID];
__device__ float g_act[NN_MAX * HID];
__device__ int   g_part[256];

// side stream + events for CSR/GEMM1 overlap (created once at load time;
// no device memory involved)
static cudaStream_t g_s2 = nullptr;
static cudaEvent_t  g_ev0 = nullptr, g_ev1 = nullptr;
namespace {
struct SideInit {
    SideInit() {
        cudaStreamCreateWithFlags(&g_s2, cudaStreamNonBlocking);
        cudaEventCreateWithFlags(&g_ev0, cudaEventDisableTiming);
        cudaEventCreateWithFlags(&g_ev1, cudaEventDisableTiming);
    }
};
SideInit g_side_init;
}

// ---------------- CSR build ----------------

__global__ void k_count(const int* __restrict__ dst, int* deg, int E) {
    int e = blockIdx.x * blockDim.x + threadIdx.x;
    if (e < E) atomicAdd(&deg[dst[e]], 1);
}

// per-block exclusive scan of deg chunk -> off, block sums -> part
__global__ void k_scan_block(const int* __restrict__ deg, int* off, int* part, int n) {
    __shared__ int s[256];
    int tid = threadIdx.x;
    int gid = blockIdx.x * 256 + tid;
    int v = (gid < n) ? deg[gid] : 0;
    s[tid] = v;
    __syncthreads();
    #pragma unroll
    for (int d = 1; d < 256; d <<= 1) {
        int t = 0;
        if (tid >= d) t = s[tid - d];
        __syncthreads();
        s[tid] += t;
        __syncthreads();
    }
    if (gid < n) off[gid] = s[tid] - v;   // exclusive within block
    if (tid == 255) part[blockIdx.x] = s[255];
}

// parallel exclusive scan of block partials (nb <= 256)
__global__ void k_scan_partials(int* part, int nb) {
    __shared__ int s[256];
    int tid = threadIdx.x;
    int v = (tid < nb) ? part[tid] : 0;
    s[tid] = v;
    __syncthreads();
    #pragma unroll
    for (int d = 1; d < 256; d <<= 1) {
        int t = (tid >= d) ? s[tid - d] : 0;
        __syncthreads();
        s[tid] += t;
        __syncthreads();
    }
    if (tid < nb) part[tid] = s[tid] - v;  // exclusive
}

__global__ void k_finalize(int* off, const int* __restrict__ part, int* cursor,
                           const int* __restrict__ deg, float* dinv, int n, int E) {
    int gid = blockIdx.x * 256 + threadIdx.x;
    if (gid < n) {
        int o = off[gid] + part[blockIdx.x];
        off[gid] = o;
        cursor[gid] = o;
        dinv[gid] = rsqrtf((float)(deg[gid] + 1));  // +1 self loop
    }
    if (gid == 0) off[n] = E;
}

__global__ void k_fill_adj(const int* __restrict__ src, const int* __restrict__ dst,
                           int* cursor, int* adj, int E) {
    int e = blockIdx.x * blockDim.x + threadIdx.x;
    if (e < E) {
        int d = dst[e];
        int pos = atomicAdd(&cursor[d], 1);
        adj[pos] = src[e];
    }
}

// ---------------- GEMM: out[i,:] = X[i,:] @ W (unscaled) ----------------
// R1 shape: block = 256 threads, 64 rows x 128 cols; thread tile 8x4.
// smem: Xs 64x128 (32KB) + Ws 32x128 chunk (16KB) = 48KB static.

__global__ __launch_bounds__(256) void k_gemm(const float* __restrict__ X,
                                              const float* __restrict__ W,
                                              float* __restrict__ out, int n) {
    __shared__ float Xs[64 * 128];
    __shared__ float Ws[32 * 128];
    float4* Xs4 = reinterpret_cast<float4*>(Xs);
    float4* Ws4 = reinterpret_cast<float4*>(Ws);
    const float4* Xg = reinterpret_cast<const float4*>(X);
    const float4* Wg = reinterpret_cast<const float4*>(W);

    int tid = threadIdx.x;
    int row0 = blockIdx.x * 64;

    // load X tile (guarded)
    #pragma unroll
    for (int t = 0; t < 8; ++t) {
        int idx = tid + t * 256;       // 0..2047 float4s
        int r = idx >> 5;              // row in tile
        int c4 = idx & 31;
        int grow = row0 + r;
        float4 v = make_float4(0.f, 0.f, 0.f, 0.f);
        if (grow < n) v = Xg[grow * 32 + c4];
        Xs4[idx] = v;
    }

    float4 acc[8];
    #pragma unroll
    for (int r = 0; r < 8; ++r) acc[r] = make_float4(0.f, 0.f, 0.f, 0.f);

    int tc = tid & 31;          // col group: columns tc*4..tc*4+3
    int tr = (tid >> 5) * 8;    // row base within tile

    #pragma unroll
    for (int kt = 0; kt < 4; ++kt) {
        __syncthreads();
        // load W chunk rows [kt*32, kt*32+32)
        #pragma unroll
        for (int t = 0; t < 4; ++t) {
            int idx = tid + t * 256;   // 0..1023
            Ws4[idx] = Wg[kt * 1024 + idx];
        }
        __syncthreads();
        #pragma unroll
        for (int k4 = 0; k4 < 8; ++k4) {
            float4 w0 = Ws4[(k4 * 4 + 0) * 32 + tc];
            float4 w1 = Ws4[(k4 * 4 + 1) * 32 + tc];
            float4 w2 = Ws4[(k4 * 4 + 2) * 32 + tc];
            float4 w3 = Ws4[(k4 * 4 + 3) * 32 + tc];
            #pragma unroll
            for (int r = 0; r < 8; ++r) {
                float4 xv = Xs4[(tr + r) * 32 + kt * 8 + k4];
                acc[r].x += xv.x * w0.x; acc[r].y += xv.x * w0.y;
                acc[r].z += xv.x * w0.z; acc[r].w += xv.x * w0.w;
                acc[r].x += xv.y * w1.x; acc[r].y += xv.y * w1.y;
                acc[r].z += xv.y * w1.z; acc[r].w += xv.y * w1.w;
                acc[r].x += xv.z * w2.x; acc[r].y += xv.z * w2.y;
                acc[r].z += xv.z * w2.z; acc[r].w += xv.z * w2.w;
                acc[r].x += xv.w * w3.x; acc[r].y += xv.w * w3.y;
                acc[r].z += xv.w * w3.z; acc[r].w += xv.w * w3.w;
            }
        }
    }

    float4* Og = reinterpret_cast<float4*>(out);
    #pragma unroll
    for (int r = 0; r < 8; ++r) {
        int grow = row0 + tr + r;
        if (grow < n) Og[grow * 32 + tc] = acc[r];
    }
}

// ---------------- Aggregation + bias + LayerNorm + ReLU ----------------
// One 128-thread block per node. ht is UNSCALED; dinv applied per-neighbor.
// out[i] = LN( dinv[i]*( sum_j dinv[j]*ht[j] + dinv[i]*ht[i] ) + b )

__device__ __forceinline__ float block_reduce_128(float v, float* sh) {
    #pragma unroll
    for (int o = 16; o; o >>= 1) v += __shfl_xor_sync(0xffffffffu, v, o);
    int w = threadIdx.x >> 5;
    if ((threadIdx.x & 31) == 0) sh[w] = v;
    __syncthreads();
    float r = sh[0] + sh[1] + sh[2] + sh[3];
    __syncthreads();
    return r;
}

__global__ void k_agg_ln(const float* __restrict__ ht, const int* __restrict__ adj,
                         const int* __restrict__ off, const float* __restrict__ dinv,
                         const float* __restrict__ bias, const float* __restrict__ gamma,
                         const float* __restrict__ beta, float* __restrict__ out, int n) {
    __shared__ float sh[4];
    int i = blockIdx.x;
    if (i >= n) return;
    int c = threadIdx.x;

    float di = __ldg(&dinv[i]);
    float a = di * __ldg(&ht[i * HID + c]);   // self-loop term
    int s = __ldg(&off[i]), e = __ldg(&off[i + 1]);
    int p = s;
    for (; p + 4 <= e; p += 4) {
        int j0 = __ldg(&adj[p]);
        int j1 = __ldg(&adj[p + 1]);
        int j2 = __ldg(&adj[p + 2]);
        int j3 = __ldg(&adj[p + 3]);
        float s0 = __ldg(&dinv[j0]);
        float s1 = __ldg(&dinv[j1]);
        float s2 = __ldg(&dinv[j2]);
        float s3 = __ldg(&dinv[j3]);
        float v0 = __ldg(&ht[j0 * HID + c]);
        float v1 = __ldg(&ht[j1 * HID + c]);
        float v2 = __ldg(&ht[j2 * HID + c]);
        float v3 = __ldg(&ht[j3 * HID + c]);
        a = fmaf(s0, v0, a);
        a = fmaf(s1, v1, a);
        a = fmaf(s2, v2, a);
        a = fmaf(s3, v3, a);
    }
    for (; p < e; ++p) {
        int j = __ldg(&adj[p]);
        a = fmaf(__ldg(&dinv[j]), __ldg(&ht[j * HID + c]), a);
    }

    float v = a * di + bias[c];

    float mu = block_reduce_128(v, sh) * (1.0f / 128.0f);
    float d = v - mu;
    float var = block_reduce_128(d * d, sh) * (1.0f / 128.0f);
    float r = d * rsqrtf(var + 1e-5f) * gamma[c] + beta[c];
    out[i * HID + c] = fmaxf(r, 0.0f);
}

// ---------------- launch ----------------

extern "C" void kernel_launch(void* const* d_in, const int* in_sizes, int n_in,
                              void* d_out, int out_size) {
    const float* x     = (const float*)d_in[0];
    const int*   edges = (const int*)d_in[1];
    const float* W1    = (const float*)d_in[2];
    const float* b1    = (const float*)d_in[3];
    const float* g1    = (const float*)d_in[4];
    const float* be1   = (const float*)d_in[5];
    const float* W2    = (const float*)d_in[6];
    const float* b2    = (const float*)d_in[7];
    const float* g2    = (const float*)d_in[8];
    const float* be2   = (const float*)d_in[9];
    float* out = (float*)d_out;

    int n = in_sizes[0] / HID;
    int E = in_sizes[1] / 2;
    const int* src = edges;
    const int* dst = edges + E;

    int *deg, *off, *cursor, *adj, *part;
    float *dinv, *ht, *act;
    cudaGetSymbolAddress((void**)&deg, g_deg);
    cudaGetSymbolAddress((void**)&off, g_off);
    cudaGetSymbolAddress((void**)&cursor, g_cursor);
    cudaGetSymbolAddress((void**)&adj, g_adj);
    cudaGetSymbolAddress((void**)&part, g_part);
    cudaGetSymbolAddress((void**)&dinv, g_dinv);
    cudaGetSymbolAddress((void**)&ht, g_ht);
    cudaGetSymbolAddress((void**)&act, g_act);

    int nbN = (n + 255) / 256;
    int nbE = (E + 255) / 256;
    int nbG = (n + 63) / 64;

    bool fork = (g_s2 != nullptr && g_ev0 != nullptr && g_ev1 != nullptr);
    cudaStream_t sc = fork ? g_s2 : (cudaStream_t)0;  // CSR stream

    if (fork) {
        cudaEventRecord(g_ev0, 0);
        cudaStreamWaitEvent(g_s2, g_ev0, 0);
    }

    // --- CSR build on side stream (independent of GEMM1) ---
    cudaMemsetAsync(deg, 0, n * sizeof(int), sc);
    k_count<<<nbE, 256, 0, sc>>>(dst, deg, E);
    k_scan_block<<<nbN, 256, 0, sc>>>(deg, off, part, n);
    k_scan_partials<<<1, 256, 0, sc>>>(part, nbN);
    k_finalize<<<nbN, 256, 0, sc>>>(off, part, cursor, deg, dinv, n, E);
    k_fill_adj<<<nbE, 256, 0, sc>>>(src, dst, cursor, adj, E);

    // --- GEMM1 on main stream, concurrent with CSR build ---
    k_gemm<<<nbG, 256>>>(x, W1, ht, n);

    if (fork) {
        cudaEventRecord(g_ev1, g_s2);
        cudaStreamWaitEvent((cudaStream_t)0, g_ev1, 0);
    }

    // --- rest serial on main stream ---
    k_agg_ln<<<n, 128>>>(ht, adj, off, dinv, b1, g1, be1, act, n);
    k_gemm<<<nbG, 256>>>(act, W2, ht, n);
    k_agg_ln<<<n, 128>>>(ht, adj, off, dinv, b2, g2, be2, out, n);
}

// round 5
// speedup vs baseline: 1.4233x; 1.3173x over previous
#include <cuda_runtime.h>
#include <cuda_bf16.h>
#include <cstdint>

#define NN_MAX 50000
#define NE_MAX 800000
#define HID 128

// ---------------- scratch (device globals) ----------------
__device__ int   g_deg[NN_MAX];
__device__ int   g_off[NN_MAX + 1];
__device__ int   g_cursor[NN_MAX];
__device__ int   g_adj[NE_MAX];
__device__ float g_dinv[NN_MAX];
__device__ float g_ht[NN_MAX * HID];
__device__ float g_act[NN_MAX * HID];
__device__ int   g_part[256];
// W hi/lo bf16, [K][N] row-major (k rows, n cols)
__device__ unsigned short g_Whi1[HID * HID];
__device__ unsigned short g_Wlo1[HID * HID];
__device__ unsigned short g_Whi2[HID * HID];
__device__ unsigned short g_Wlo2[HID * HID];

// ---------------- CSR build ----------------
__global__ void k_count(const int* __restrict__ dst, int* deg, int E) {
    int e = blockIdx.x * blockDim.x + threadIdx.x;
    if (e < E) atomicAdd(&deg[dst[e]], 1);
}

__global__ void k_scan_block(const int* __restrict__ deg, int* off, int* part, int n) {
    __shared__ int s[256];
    int tid = threadIdx.x;
    int gid = blockIdx.x * 256 + tid;
    int v = (gid < n) ? deg[gid] : 0;
    s[tid] = v;
    __syncthreads();
    #pragma unroll
    for (int d = 1; d < 256; d <<= 1) {
        int t = 0;
        if (tid >= d) t = s[tid - d];
        __syncthreads();
        s[tid] += t;
        __syncthreads();
    }
    if (gid < n) off[gid] = s[tid] - v;
    if (tid == 255) part[blockIdx.x] = s[255];
}

__global__ void k_scan_partials(int* part, int nb) {
    __shared__ int s[256];
    int tid = threadIdx.x;
    int v = (tid < nb) ? part[tid] : 0;
    s[tid] = v;
    __syncthreads();
    #pragma unroll
    for (int d = 1; d < 256; d <<= 1) {
        int t = (tid >= d) ? s[tid - d] : 0;
        __syncthreads();
        s[tid] += t;
        __syncthreads();
    }
    if (tid < nb) part[tid] = s[tid] - v;
}

__global__ void k_finalize(int* off, const int* __restrict__ part, int* cursor,
                           const int* __restrict__ deg, float* dinv, int n, int E) {
    int gid = blockIdx.x * 256 + threadIdx.x;
    if (gid < n) {
        int o = off[gid] + part[blockIdx.x];
        off[gid] = o;
        cursor[gid] = o;
        dinv[gid] = rsqrtf((float)(deg[gid] + 1));
    }
    if (gid == 0) off[n] = E;
}

__global__ void k_fill_adj(const int* __restrict__ src, const int* __restrict__ dst,
                           int* cursor, int* adj, int E) {
    int e = blockIdx.x * blockDim.x + threadIdx.x;
    if (e < E) {
        int d = dst[e];
        int pos = atomicAdd(&cursor[d], 1);
        adj[pos] = src[e];
    }
}

// ---------------- W prep: fp32 [K][N] -> bf16 hi/lo [K][N] ----------------
__global__ void k_prepW(const float* __restrict__ W, unsigned short* hi, unsigned short* lo) {
    int e = blockIdx.x * 256 + threadIdx.x;
    if (e >= HID * HID) return;
    float w = W[e];
    __nv_bfloat16 h = __float2bfloat16(w);
    float r = w - __bfloat162float(h);
    __nv_bfloat16 l = __float2bfloat16(r);
    hi[e] = __bfloat16_as_ushort(h);
    lo[e] = __bfloat16_as_ushort(l);
}

// ---------------- HMMA GEMM: out[i,:] = (X[i,:] @ W) * dinv[i] ----------------
// 256 threads / 8 warps; CTA = 128 rows. Warp w: rows w*16..w*16+15, all 128 cols.
// A hi/lo and B(W) hi/lo tiles in smem, rows padded to 136 bf16 (272B).

#define LDA 136
#define TILE_B (128 * LDA * 2)       // 34816 bytes per tile
#define GEMM_SMEM (4 * TILE_B)       // 139264

__device__ __forceinline__ uint32_t smem_u32(const void* p) {
    uint32_t a;
    asm("{ .reg .u64 t; cvta.to.shared.u64 t, %1; cvt.u32.u64 %0, t; }" : "=r"(a) : "l"(p));
    return a;
}

__device__ __forceinline__ void ldsm_x4(uint32_t* r, uint32_t addr) {
    asm volatile("ldmatrix.sync.aligned.m8n8.x4.shared.b16 {%0,%1,%2,%3}, [%4];"
                 : "=r"(r[0]), "=r"(r[1]), "=r"(r[2]), "=r"(r[3]) : "r"(addr));
}
__device__ __forceinline__ void ldsm_x2t(uint32_t* r, uint32_t addr) {
    asm volatile("ldmatrix.sync.aligned.m8n8.x2.trans.shared.b16 {%0,%1}, [%2];"
                 : "=r"(r[0]), "=r"(r[1]) : "r"(addr));
}
__device__ __forceinline__ void mma_bf16(float* c, const uint32_t* a, const uint32_t* b) {
    asm volatile("mma.sync.aligned.m16n8k16.row.col.f32.bf16.bf16.f32 "
                 "{%0,%1,%2,%3}, {%4,%5,%6,%7}, {%8,%9}, {%0,%1,%2,%3};"
                 : "+f"(c[0]), "+f"(c[1]), "+f"(c[2]), "+f"(c[3])
                 : "r"(a[0]), "r"(a[1]), "r"(a[2]), "r"(a[3]), "r"(b[0]), "r"(b[1]));
}

__global__ __launch_bounds__(256, 1)
void k_gemm_mma(const float* __restrict__ X,
                const unsigned short* __restrict__ Whi,
                const unsigned short* __restrict__ Wlo,
                const float* __restrict__ dinv,
                float* __restrict__ out, int n)
{
    extern __shared__ char sm[];
    char* pAhi = sm;
    char* pAlo = sm + TILE_B;
    char* pBhi = sm + 2 * TILE_B;
    char* pBlo = sm + 3 * TILE_B;
    uint32_t uAhi = smem_u32(pAhi), uAlo = smem_u32(pAlo);
    uint32_t uBhi = smem_u32(pBhi), uBlo = smem_u32(pBlo);

    int tid = threadIdx.x, wid = tid >> 5, lid = tid & 31;
    int row0 = blockIdx.x * 128;

    // --- copy W hi/lo [K][N] -> smem padded rows (16 uint4 per row, stride 17) ---
    {
        const uint4* sh = (const uint4*)Whi;
        const uint4* sl = (const uint4*)Wlo;
        uint4* dh = (uint4*)pBhi;
        uint4* dl = (uint4*)pBlo;
        #pragma unroll
        for (int i = 0; i < 8; ++i) {
            int idx = i * 256 + tid;       // 0..2047
            int k = idx >> 4, g = idx & 15;
            dh[k * 17 + g] = sh[idx];
            dl[k * 17 + g] = sl[idx];
        }
    }

    // --- convert X tile fp32 -> bf16 hi/lo, padded rows ---
    {
        const float4* Xg = (const float4*)X;
        #pragma unroll
        for (int i = 0; i < 8; ++i) {
            int idx = i * 256 + tid;       // 0..2047 groups of 8 floats
            int r = idx >> 4, g = idx & 15;
            int grow = row0 + r;
            float4 v0 = make_float4(0.f, 0.f, 0.f, 0.f);
            float4 v1 = make_float4(0.f, 0.f, 0.f, 0.f);
            if (grow < n) {
                v0 = __ldg(&Xg[grow * 32 + g * 2]);
                v1 = __ldg(&Xg[grow * 32 + g * 2 + 1]);
            }
            float f[8] = {v0.x, v0.y, v0.z, v0.w, v1.x, v1.y, v1.z, v1.w};
            uint32_t ph[4], pl[4];
            #pragma unroll
            for (int q = 0; q < 4; ++q) {
                __nv_bfloat16 h0 = __float2bfloat16(f[q * 2]);
                __nv_bfloat16 h1 = __float2bfloat16(f[q * 2 + 1]);
                float r0 = f[q * 2]     - __bfloat162float(h0);
                float r1 = f[q * 2 + 1] - __bfloat162float(h1);
                __nv_bfloat16 l0 = __float2bfloat16(r0);
                __nv_bfloat16 l1 = __float2bfloat16(r1);
                ph[q] = ((uint32_t)__bfloat16_as_ushort(h1) << 16) | __bfloat16_as_ushort(h0);
                pl[q] = ((uint32_t)__bfloat16_as_ushort(l1) << 16) | __bfloat16_as_ushort(l0);
            }
            uint4* dh = (uint4*)pAhi;
            uint4* dl = (uint4*)pAlo;
            dh[r * 17 + g] = make_uint4(ph[0], ph[1], ph[2], ph[3]);
            dl[r * 17 + g] = make_uint4(pl[0], pl[1], pl[2], pl[3]);
        }
    }
    __syncthreads();

    // --- mainloop ---
    int m0 = wid * 16;
    float c[16][4];
    #pragma unroll
    for (int t = 0; t < 16; ++t)
        #pragma unroll
        for (int q = 0; q < 4; ++q) c[t][q] = 0.f;

    // A ldmatrix lane address components
    int a_row = m0 + (lid & 15);
    int a_k8  = (lid >> 4) * 8;
    // B ldmatrix lane address: row = kbase + (lid&15), col nt*8
    int b_row = (lid & 15);

    #pragma unroll
    for (int ks = 0; ks < 8; ++ks) {
        int kb = ks * 16;
        uint32_t ahi[4], alo[4];
        uint32_t a_off = ((uint32_t)(a_row * LDA + kb + a_k8)) * 2u;
        ldsm_x4(ahi, uAhi + a_off);
        ldsm_x4(alo, uAlo + a_off);

        uint32_t b_base = ((uint32_t)((kb + b_row) * LDA)) * 2u;
        #pragma unroll
        for (int nt = 0; nt < 16; ++nt) {
            uint32_t bhi[2], blo[2];
            uint32_t b_off = b_base + nt * 16u;
            ldsm_x2t(bhi, uBhi + b_off);
            ldsm_x2t(blo, uBlo + b_off);
            mma_bf16(c[nt], ahi, bhi);
            mma_bf16(c[nt], ahi, blo);
            mma_bf16(c[nt], alo, bhi);
        }
    }

    // --- epilogue: scale by dinv, store fp32 ---
    {
        int ml = lid >> 2;            // 0..7
        int n0 = (lid & 3) * 2;
        int r0g = row0 + m0 + ml;
        int r1g = r0g + 8;
        float s0 = (r0g < n) ? dinv[r0g] : 0.f;
        float s1 = (r1g < n) ? dinv[r1g] : 0.f;
        #pragma unroll
        for (int nt = 0; nt < 16; ++nt) {
            int col = nt * 8 + n0;
            if (r0g < n) {
                float2 v = make_float2(c[nt][0] * s0, c[nt][1] * s0);
                *(float2*)(out + (size_t)r0g * HID + col) = v;
            }
            if (r1g < n) {
                float2 v = make_float2(c[nt][2] * s1, c[nt][3] * s1);
                *(float2*)(out + (size_t)r1g * HID + col) = v;
            }
        }
    }
}

// ---------------- Aggregation + bias + LayerNorm + ReLU ----------------
__device__ __forceinline__ float block_reduce_128(float v, float* sh) {
    #pragma unroll
    for (int o = 16; o; o >>= 1) v += __shfl_xor_sync(0xffffffffu, v, o);
    int w = threadIdx.x >> 5;
    if ((threadIdx.x & 31) == 0) sh[w] = v;
    __syncthreads();
    float r = sh[0] + sh[1] + sh[2] + sh[3];
    __syncthreads();
    return r;
}

__global__ void k_agg_ln(const float* __restrict__ ht, const int* __restrict__ adj,
                         const int* __restrict__ off, const float* __restrict__ dinv,
                         const float* __restrict__ bias, const float* __restrict__ gamma,
                         const float* __restrict__ beta, float* __restrict__ out, int n) {
    __shared__ float sh[4];
    int i = blockIdx.x;
    if (i >= n) return;
    int c = threadIdx.x;

    float a = __ldg(&ht[i * HID + c]);      // self-loop term (pre-scaled)
    int s = __ldg(&off[i]), e = __ldg(&off[i + 1]);
    int p = s;
    for (; p + 4 <= e; p += 4) {
        int j0 = __ldg(&adj[p]);
        int j1 = __ldg(&adj[p + 1]);
        int j2 = __ldg(&adj[p + 2]);
        int j3 = __ldg(&adj[p + 3]);
        float v0 = __ldg(&ht[j0 * HID + c]);
        float v1 = __ldg(&ht[j1 * HID + c]);
        float v2 = __ldg(&ht[j2 * HID + c]);
        float v3 = __ldg(&ht[j3 * HID + c]);
        a += (v0 + v1) + (v2 + v3);
    }
    for (; p < e; ++p) a += __ldg(&ht[__ldg(&adj[p]) * HID + c]);

    float v = a * dinv[i] + bias[c];

    float mu = block_reduce_128(v, sh) * (1.0f / 128.0f);
    float d = v - mu;
    float var = block_reduce_128(d * d, sh) * (1.0f / 128.0f);
    float r = d * rsqrtf(var + 1e-5f) * gamma[c] + beta[c];
    out[i * HID + c] = fmaxf(r, 0.0f);
}

// ---------------- launch ----------------
extern "C" void kernel_launch(void* const* d_in, const int* in_sizes, int n_in,
                              void* d_out, int out_size) {
    const float* x     = (const float*)d_in[0];
    const int*   edges = (const int*)d_in[1];
    const float* W1    = (const float*)d_in[2];
    const float* b1    = (const float*)d_in[3];
    const float* g1    = (const float*)d_in[4];
    const float* be1   = (const float*)d_in[5];
    const float* W2    = (const float*)d_in[6];
    const float* b2    = (const float*)d_in[7];
    const float* g2    = (const float*)d_in[8];
    const float* be2   = (const float*)d_in[9];
    float* out = (float*)d_out;

    int n = in_sizes[0] / HID;
    int E = in_sizes[1] / 2;
    const int* src = edges;
    const int* dst = edges + E;

    int *deg, *off, *cursor, *adj, *part;
    float *dinv, *ht, *act;
    unsigned short *whi1, *wlo1, *whi2, *wlo2;
    cudaGetSymbolAddress((void**)&deg, g_deg);
    cudaGetSymbolAddress((void**)&off, g_off);
    cudaGetSymbolAddress((void**)&cursor, g_cursor);
    cudaGetSymbolAddress((void**)&adj, g_adj);
    cudaGetSymbolAddress((void**)&part, g_part);
    cudaGetSymbolAddress((void**)&dinv, g_dinv);
    cudaGetSymbolAddress((void**)&ht, g_ht);
    cudaGetSymbolAddress((void**)&act, g_act);
    cudaGetSymbolAddress((void**)&whi1, g_Whi1);
    cudaGetSymbolAddress((void**)&wlo1, g_Wlo1);
    cudaGetSymbolAddress((void**)&whi2, g_Whi2);
    cudaGetSymbolAddress((void**)&wlo2, g_Wlo2);

    static bool attr_done = false;
    if (!attr_done) {
        cudaFuncSetAttribute(k_gemm_mma, cudaFuncAttributeMaxDynamicSharedMemorySize, GEMM_SMEM);
        attr_done = true;
    }

    int nbN = (n + 255) / 256;
    int nbE = (E + 255) / 256;
    int nbG = (n + 127) / 128;

    // W prep
    k_prepW<<<64, 256>>>(W1, whi1, wlo1);
    k_prepW<<<64, 256>>>(W2, whi2, wlo2);

    // CSR build
    cudaMemsetAsync(deg, 0, n * sizeof(int));
    k_count<<<nbE, 256>>>(dst, deg, E);
    k_scan_block<<<nbN, 256>>>(deg, off, part, n);
    k_scan_partials<<<1, 256>>>(part, nbN);
    k_finalize<<<nbN, 256>>>(off, part, cursor, deg, dinv, n, E);
    k_fill_adj<<<nbE, 256>>>(src, dst, cursor, adj, E);

    // layer 1
    k_gemm_mma<<<nbG, 256, GEMM_SMEM>>>(x, whi1, wlo1, dinv, ht, n);
    k_agg_ln<<<n, 128>>>(ht, adj, off, dinv, b1, g1, be1, act, n);
    // layer 2
    k_gemm_mma<<<nbG, 256, GEMM_SMEM>>>(act, whi2, wlo2, dinv, ht, n);
    k_agg_ln<<<n, 128>>>(ht, adj, off, dinv, b2, g2, be2, out, n);
}

// round 6
// speedup vs baseline: 1.8496x; 1.2995x over previous
#include <cuda_runtime.h>
#include <cuda_bf16.h>
#include <cuda_fp16.h>
#include <cstdint>

#define NN_MAX 50000
#define NE_MAX 800000
#define HID 128

// ---------------- scratch (device globals) ----------------
__device__ int    g_deg[NN_MAX];
__device__ int    g_off[NN_MAX + 1];
__device__ int    g_cursor[NN_MAX];
__device__ int    g_adj[NE_MAX];
__device__ float  g_dinv[NN_MAX];
__device__ __half g_ht[NN_MAX * HID];     // GEMM output, fp16, pre-scaled by dinv
__device__ float  g_act[NN_MAX * HID];    // post-LN activations, fp32
__device__ int    g_part[256];
// W hi/lo bf16, [K][N] row-major
__device__ unsigned short g_Whi1[HID * HID];
__device__ unsigned short g_Wlo1[HID * HID];
__device__ unsigned short g_Whi2[HID * HID];
__device__ unsigned short g_Wlo2[HID * HID];

// ---------------- CSR build ----------------
__global__ void k_count(const int* __restrict__ dst, int* deg, int E) {
    int e = blockIdx.x * blockDim.x + threadIdx.x;
    if (e < E) atomicAdd(&deg[dst[e]], 1);
}

__global__ void k_scan_block(const int* __restrict__ deg, int* off, int* part, int n) {
    __shared__ int s[256];
    int tid = threadIdx.x;
    int gid = blockIdx.x * 256 + tid;
    int v = (gid < n) ? deg[gid] : 0;
    s[tid] = v;
    __syncthreads();
    #pragma unroll
    for (int d = 1; d < 256; d <<= 1) {
        int t = 0;
        if (tid >= d) t = s[tid - d];
        __syncthreads();
        s[tid] += t;
        __syncthreads();
    }
    if (gid < n) off[gid] = s[tid] - v;
    if (tid == 255) part[blockIdx.x] = s[255];
}

__global__ void k_scan_partials(int* part, int nb) {
    __shared__ int s[256];
    int tid = threadIdx.x;
    int v = (tid < nb) ? part[tid] : 0;
    s[tid] = v;
    __syncthreads();
    #pragma unroll
    for (int d = 1; d < 256; d <<= 1) {
        int t = (tid >= d) ? s[tid - d] : 0;
        __syncthreads();
        s[tid] += t;
        __syncthreads();
    }
    if (tid < nb) part[tid] = s[tid] - v;
}

__global__ void k_finalize(int* off, const int* __restrict__ part, int* cursor,
                           const int* __restrict__ deg, float* dinv, int n, int E) {
    int gid = blockIdx.x * 256 + threadIdx.x;
    if (gid < n) {
        int o = off[gid] + part[blockIdx.x];
        off[gid] = o;
        cursor[gid] = o;
        dinv[gid] = rsqrtf((float)(deg[gid] + 1));
    }
    if (gid == 0) off[n] = E;
}

__global__ void k_fill_adj(const int* __restrict__ src, const int* __restrict__ dst,
                           int* cursor, int* adj, int E) {
    int e = blockIdx.x * blockDim.x + threadIdx.x;
    if (e < E) {
        int d = dst[e];
        int pos = atomicAdd(&cursor[d], 1);
        adj[pos] = src[e];
    }
}

// ---------------- W prep: fp32 [K][N] -> bf16 hi/lo [K][N] ----------------
__global__ void k_prepW(const float* __restrict__ W, unsigned short* hi, unsigned short* lo) {
    int e = blockIdx.x * 256 + threadIdx.x;
    if (e >= HID * HID) return;
    float w = W[e];
    __nv_bfloat16 h = __float2bfloat16(w);
    float r = w - __bfloat162float(h);
    __nv_bfloat16 l = __float2bfloat16(r);
    hi[e] = __bfloat16_as_ushort(h);
    lo[e] = __bfloat16_as_ushort(l);
}

// ---------------- HMMA GEMM: ht[i,:] = fp16( (X[i,:] @ W) * dinv[i] ) ----------------
#define LDA 136
#define TILE_B (128 * LDA * 2)       // 34816 bytes per tile
#define GEMM_SMEM (4 * TILE_B)       // 139264

__device__ __forceinline__ uint32_t smem_u32(const void* p) {
    uint32_t a;
    asm("{ .reg .u64 t; cvta.to.shared.u64 t, %1; cvt.u32.u64 %0, t; }" : "=r"(a) : "l"(p));
    return a;
}

__device__ __forceinline__ void ldsm_x4(uint32_t* r, uint32_t addr) {
    asm volatile("ldmatrix.sync.aligned.m8n8.x4.shared.b16 {%0,%1,%2,%3}, [%4];"
                 : "=r"(r[0]), "=r"(r[1]), "=r"(r[2]), "=r"(r[3]) : "r"(addr));
}
__device__ __forceinline__ void ldsm_x2t(uint32_t* r, uint32_t addr) {
    asm volatile("ldmatrix.sync.aligned.m8n8.x2.trans.shared.b16 {%0,%1}, [%2];"
                 : "=r"(r[0]), "=r"(r[1]) : "r"(addr));
}
__device__ __forceinline__ void mma_bf16(float* c, const uint32_t* a, const uint32_t* b) {
    asm volatile("mma.sync.aligned.m16n8k16.row.col.f32.bf16.bf16.f32 "
                 "{%0,%1,%2,%3}, {%4,%5,%6,%7}, {%8,%9}, {%0,%1,%2,%3};"
                 : "+f"(c[0]), "+f"(c[1]), "+f"(c[2]), "+f"(c[3])
                 : "r"(a[0]), "r"(a[1]), "r"(a[2]), "r"(a[3]), "r"(b[0]), "r"(b[1]));
}

__global__ __launch_bounds__(256, 1)
void k_gemm_mma(const float* __restrict__ X,
                const unsigned short* __restrict__ Whi,
                const unsigned short* __restrict__ Wlo,
                const float* __restrict__ dinv,
                __half* __restrict__ out, int n)
{
    extern __shared__ char sm[];
    char* pAhi = sm;
    char* pAlo = sm + TILE_B;
    char* pBhi = sm + 2 * TILE_B;
    char* pBlo = sm + 3 * TILE_B;
    uint32_t uAhi = smem_u32(pAhi), uAlo = smem_u32(pAlo);
    uint32_t uBhi = smem_u32(pBhi), uBlo = smem_u32(pBlo);

    int tid = threadIdx.x, wid = tid >> 5, lid = tid & 31;
    int row0 = blockIdx.x * 128;

    // copy W hi/lo into smem (padded rows)
    {
        const uint4* sh = (const uint4*)Whi;
        const uint4* sl = (const uint4*)Wlo;
        uint4* dh = (uint4*)pBhi;
        uint4* dl = (uint4*)pBlo;
        #pragma unroll
        for (int i = 0; i < 8; ++i) {
            int idx = i * 256 + tid;
            int k = idx >> 4, g = idx & 15;
            dh[k * 17 + g] = sh[idx];
            dl[k * 17 + g] = sl[idx];
        }
    }

    // convert X tile fp32 -> bf16 hi/lo
    {
        const float4* Xg = (const float4*)X;
        #pragma unroll
        for (int i = 0; i < 8; ++i) {
            int idx = i * 256 + tid;
            int r = idx >> 4, g = idx & 15;
            int grow = row0 + r;
            float4 v0 = make_float4(0.f, 0.f, 0.f, 0.f);
            float4 v1 = make_float4(0.f, 0.f, 0.f, 0.f);
            if (grow < n) {
                v0 = __ldg(&Xg[grow * 32 + g * 2]);
                v1 = __ldg(&Xg[grow * 32 + g * 2 + 1]);
            }
            float f[8] = {v0.x, v0.y, v0.z, v0.w, v1.x, v1.y, v1.z, v1.w};
            uint32_t ph[4], pl[4];
            #pragma unroll
            for (int q = 0; q < 4; ++q) {
                __nv_bfloat16 h0 = __float2bfloat16(f[q * 2]);
                __nv_bfloat16 h1 = __float2bfloat16(f[q * 2 + 1]);
                float r0 = f[q * 2]     - __bfloat162float(h0);
                float r1 = f[q * 2 + 1] - __bfloat162float(h1);
                __nv_bfloat16 l0 = __float2bfloat16(r0);
                __nv_bfloat16 l1 = __float2bfloat16(r1);
                ph[q] = ((uint32_t)__bfloat16_as_ushort(h1) << 16) | __bfloat16_as_ushort(h0);
                pl[q] = ((uint32_t)__bfloat16_as_ushort(l1) << 16) | __bfloat16_as_ushort(l0);
            }
            uint4* dh = (uint4*)pAhi;
            uint4* dl = (uint4*)pAlo;
            dh[r * 17 + g] = make_uint4(ph[0], ph[1], ph[2], ph[3]);
            dl[r * 17 + g] = make_uint4(pl[0], pl[1], pl[2], pl[3]);
        }
    }
    __syncthreads();

    // mainloop
    int m0 = wid * 16;
    float c[16][4];
    #pragma unroll
    for (int t = 0; t < 16; ++t)
        #pragma unroll
        for (int q = 0; q < 4; ++q) c[t][q] = 0.f;

    int a_row = m0 + (lid & 15);
    int a_k8  = (lid >> 4) * 8;
    int b_row = (lid & 15);

    #pragma unroll
    for (int ks = 0; ks < 8; ++ks) {
        int kb = ks * 16;
        uint32_t ahi[4], alo[4];
        uint32_t a_off = ((uint32_t)(a_row * LDA + kb + a_k8)) * 2u;
        ldsm_x4(ahi, uAhi + a_off);
        ldsm_x4(alo, uAlo + a_off);

        uint32_t b_base = ((uint32_t)((kb + b_row) * LDA)) * 2u;
        #pragma unroll
        for (int nt = 0; nt < 16; ++nt) {
            uint32_t bhi[2], blo[2];
            uint32_t b_off = b_base + nt * 16u;
            ldsm_x2t(bhi, uBhi + b_off);
            ldsm_x2t(blo, uBlo + b_off);
            mma_bf16(c[nt], ahi, bhi);
            mma_bf16(c[nt], ahi, blo);
            mma_bf16(c[nt], alo, bhi);
        }
    }

    // epilogue: scale by dinv, store fp16
    {
        int ml = lid >> 2;
        int n0 = (lid & 3) * 2;
        int r0g = row0 + m0 + ml;
        int r1g = r0g + 8;
        float s0 = (r0g < n) ? dinv[r0g] : 0.f;
        float s1 = (r1g < n) ? dinv[r1g] : 0.f;
        #pragma unroll
        for (int nt = 0; nt < 16; ++nt) {
            int col = nt * 8 + n0;
            if (r0g < n) {
                __half2 h = __floats2half2_rn(c[nt][0] * s0, c[nt][1] * s0);
                *(__half2*)(out + (size_t)r0g * HID + col) = h;
            }
            if (r1g < n) {
                __half2 h = __floats2half2_rn(c[nt][2] * s1, c[nt][3] * s1);
                *(__half2*)(out + (size_t)r1g * HID + col) = h;
            }
        }
    }
}

// ---------------- Aggregation + bias + LayerNorm + ReLU ----------------
// 64 threads per node; thread c handles cols 2c, 2c+1 via half2.

__device__ __forceinline__ float block_reduce_64(float v, float* sh) {
    #pragma unroll
    for (int o = 16; o; o >>= 1) v += __shfl_xor_sync(0xffffffffu, v, o);
    int w = threadIdx.x >> 5;
    if ((threadIdx.x & 31) == 0) sh[w] = v;
    __syncthreads();
    float r = sh[0] + sh[1];
    __syncthreads();
    return r;
}

__global__ __launch_bounds__(64)
void k_agg_ln(const __half2* __restrict__ ht2, const int* __restrict__ adj,
              const int* __restrict__ off, const float* __restrict__ dinv,
              const float* __restrict__ bias, const float* __restrict__ gamma,
              const float* __restrict__ beta, float* __restrict__ out, int n) {
    __shared__ float sh[2];
    int i = blockIdx.x;
    if (i >= n) return;
    int c = threadIdx.x;   // 0..63

    float2 a = __half22float2(__ldg(&ht2[(size_t)i * 64 + c]));  // self loop
    int s = __ldg(&off[i]), e = __ldg(&off[i + 1]);
    int p = s;
    for (; p + 4 <= e; p += 4) {
        int j0 = __ldg(&adj[p]);
        int j1 = __ldg(&adj[p + 1]);
        int j2 = __ldg(&adj[p + 2]);
        int j3 = __ldg(&adj[p + 3]);
        float2 v0 = __half22float2(__ldg(&ht2[(size_t)j0 * 64 + c]));
        float2 v1 = __half22float2(__ldg(&ht2[(size_t)j1 * 64 + c]));
        float2 v2 = __half22float2(__ldg(&ht2[(size_t)j2 * 64 + c]));
        float2 v3 = __half22float2(__ldg(&ht2[(size_t)j3 * 64 + c]));
        a.x += (v0.x + v1.x) + (v2.x + v3.x);
        a.y += (v0.y + v1.y) + (v2.y + v3.y);
    }
    for (; p < e; ++p) {
        float2 v = __half22float2(__ldg(&ht2[(size_t)__ldg(&adj[p]) * 64 + c]));
        a.x += v.x; a.y += v.y;
    }

    float di = dinv[i];
    float2 bb = ((const float2*)bias)[c];
    float vx = a.x * di + bb.x;
    float vy = a.y * di + bb.y;

    float mu = block_reduce_64(vx + vy, sh) * (1.0f / 128.0f);
    float dx = vx - mu, dy = vy - mu;
    float var = block_reduce_64(dx * dx + dy * dy, sh) * (1.0f / 128.0f);
    float rs = rsqrtf(var + 1e-5f);
    float2 gg = ((const float2*)gamma)[c];
    float2 be = ((const float2*)beta)[c];
    float2 o = make_float2(fmaxf(dx * rs * gg.x + be.x, 0.0f),
                           fmaxf(dy * rs * gg.y + be.y, 0.0f));
    ((float2*)out)[(size_t)i * 64 + c] = o;
}

// ---------------- launch ----------------
extern "C" void kernel_launch(void* const* d_in, const int* in_sizes, int n_in,
                              void* d_out, int out_size) {
    const float* x     = (const float*)d_in[0];
    const int*   edges = (const int*)d_in[1];
    const float* W1    = (const float*)d_in[2];
    const float* b1    = (const float*)d_in[3];
    const float* g1    = (const float*)d_in[4];
    const float* be1   = (const float*)d_in[5];
    const float* W2    = (const float*)d_in[6];
    const float* b2    = (const float*)d_in[7];
    const float* g2    = (const float*)d_in[8];
    const float* be2   = (const float*)d_in[9];
    float* out = (float*)d_out;

    int n = in_sizes[0] / HID;
    int E = in_sizes[1] / 2;
    const int* src = edges;
    const int* dst = edges + E;

    int *deg, *off, *cursor, *adj, *part;
    float *dinv, *act;
    __half* ht;
    unsigned short *whi1, *wlo1, *whi2, *wlo2;
    cudaGetSymbolAddress((void**)&deg, g_deg);
    cudaGetSymbolAddress((void**)&off, g_off);
    cudaGetSymbolAddress((void**)&cursor, g_cursor);
    cudaGetSymbolAddress((void**)&adj, g_adj);
    cudaGetSymbolAddress((void**)&part, g_part);
    cudaGetSymbolAddress((void**)&dinv, g_dinv);
    cudaGetSymbolAddress((void**)&ht, g_ht);
    cudaGetSymbolAddress((void**)&act, g_act);
    cudaGetSymbolAddress((void**)&whi1, g_Whi1);
    cudaGetSymbolAddress((void**)&wlo1, g_Wlo1);
    cudaGetSymbolAddress((void**)&whi2, g_Whi2);
    cudaGetSymbolAddress((void**)&wlo2, g_Wlo2);

    static bool attr_done = false;
    if (!attr_done) {
        cudaFuncSetAttribute(k_gemm_mma, cudaFuncAttributeMaxDynamicSharedMemorySize, GEMM_SMEM);
        attr_done = true;
    }

    int nbN = (n + 255) / 256;
    int nbE = (E + 255) / 256;
    int nbG = (n + 127) / 128;

    // W prep
    k_prepW<<<64, 256>>>(W1, whi1, wlo1);
    k_prepW<<<64, 256>>>(W2, whi2, wlo2);

    // CSR build
    cudaMemsetAsync(deg, 0, n * sizeof(int));
    k_count<<<nbE, 256>>>(dst, deg, E);
    k_scan_block<<<nbN, 256>>>(deg, off, part, n);
    k_scan_partials<<<1, 256>>>(part, nbN);
    k_finalize<<<nbN, 256>>>(off, part, cursor, deg, dinv, n, E);
    k_fill_adj<<<nbE, 256>>>(src, dst, cursor, adj, E);

    // layer 1
    k_gemm_mma<<<nbG, 256, GEMM_SMEM>>>(x, whi1, wlo1, dinv, ht, n);
    k_agg_ln<<<n, 64>>>((const __half2*)ht, adj, off, dinv, b1, g1, be1, act, n);
    // layer 2
    k_gemm_mma<<<nbG, 256, GEMM_SMEM>>>(act, whi2, wlo2, dinv, ht, n);
    k_agg_ln<<<n, 64>>>((const __half2*)ht, adj, off, dinv, b2, g2, be2, out, n);
}